// round 16
// baseline (speedup 1.0000x reference)
#include <cuda_runtime.h>
#include <cuda_bf16.h>
#include <cstdint>

#define N_NODES 50000
#define N_EDGES 800000
#define D 64
#define D2 128

#define SCAN_BLK 1024
#define NBLK_SCAN 49

#define TILE_M 128
#define N_TILES ((N_NODES + TILE_M - 1) / TILE_M)   // 391

// GEMM smem layout: bf16 tiles, row stride 272B -> conflict-free ldmatrix/STS.
#define ASTRIDE 272
#define SM_AH 0
#define SM_AM (SM_AH + TILE_M * ASTRIDE)     // 34816
#define SM_BH (SM_AM + TILE_M * ASTRIDE)     // 69632
#define SM_BM (SM_BH + D * ASTRIDE)          // 87040
#define SM_TOTAL (SM_BM + D * ASTRIDE)       // 104448 -> 2 CTAs/SM

#define GATHER_BLOCKS 1184
#define HIST_BLOCKS ((N_EDGES / 4 + 255) / 256)     // 782

// ---------------------------------------------------------------------------
// Scratch
// ---------------------------------------------------------------------------
struct __align__(8) EdgeRec { int s; float w; };

__device__ int     g_count[N_NODES];
__device__ int     g_start[N_NODES];
__device__ int     g_cursor[N_NODES];
__device__ int     g_total;
__device__ EdgeRec g_edge[N_EDGES];
// bf16 hi/mid pre-split tensors, row-major [n][d], 8 bf16 per uint4
__device__ uint4   g_hh[N_NODES * D / 8];
__device__ uint4   g_hm[N_NODES * D / 8];
__device__ uint4   g_hnh[N_NODES * D / 8];
__device__ uint4   g_hnm[N_NODES * D / 8];

// ---------------------------------------------------------------------------
// helpers
// ---------------------------------------------------------------------------
__device__ __forceinline__ uint32_t s2u(const void* p) {
    uint32_t a;
    asm("{ .reg .u64 t; cvta.to.shared.u64 t, %1; cvt.u32.u64 %0, t; }" : "=r"(a) : "l"(p));
    return a;
}

__device__ __forceinline__ void ldm_x4(uint32_t& r0, uint32_t& r1,
                                       uint32_t& r2, uint32_t& r3, uint32_t a) {
    asm volatile("ldmatrix.sync.aligned.m8n8.x4.shared.b16 {%0,%1,%2,%3}, [%4];"
                 : "=r"(r0), "=r"(r1), "=r"(r2), "=r"(r3) : "r"(a));
}
__device__ __forceinline__ void ldm_x2(uint32_t& r0, uint32_t& r1, uint32_t a) {
    asm volatile("ldmatrix.sync.aligned.m8n8.x2.shared.b16 {%0,%1}, [%2];"
                 : "=r"(r0), "=r"(r1) : "r"(a));
}
__device__ __forceinline__ void mma16816(float* c, const uint32_t* a,
                                         uint32_t b0, uint32_t b1) {
    asm volatile("mma.sync.aligned.m16n8k16.row.col.f32.bf16.bf16.f32 "
                 "{%0,%1,%2,%3}, {%4,%5,%6,%7}, {%8,%9}, {%0,%1,%2,%3};"
                 : "+f"(c[0]), "+f"(c[1]), "+f"(c[2]), "+f"(c[3])
                 : "r"(a[0]), "r"(a[1]), "r"(a[2]), "r"(a[3]), "r"(b0), "r"(b1));
}

__device__ __forceinline__ void split8(const float* v, uint4& uh, uint4& um) {
    uint32_t hs[8], ms[8];
    #pragma unroll
    for (int i = 0; i < 8; i++) {
        __nv_bfloat16 hb = __float2bfloat16(v[i]);
        float rem = v[i] - __bfloat162float(hb);
        __nv_bfloat16 mb = __float2bfloat16(rem);
        hs[i] = (uint32_t)__bfloat16_as_ushort(hb);
        ms[i] = (uint32_t)__bfloat16_as_ushort(mb);
    }
    uh = make_uint4(hs[0] | (hs[1] << 16), hs[2] | (hs[3] << 16),
                    hs[4] | (hs[5] << 16), hs[6] | (hs[7] << 16));
    um = make_uint4(ms[0] | (ms[1] << 16), ms[2] | (ms[3] << 16),
                    ms[4] | (ms[5] << 16), ms[6] | (ms[7] << 16));
}

__device__ __forceinline__ void split4(float4 v, uint2& uh, uint2& um) {
    float vv[4] = {v.x, v.y, v.z, v.w};
    uint32_t hs[4], ms[4];
    #pragma unroll
    for (int i = 0; i < 4; i++) {
        __nv_bfloat16 hb = __float2bfloat16(vv[i]);
        float rem = vv[i] - __bfloat162float(hb);
        __nv_bfloat16 mb = __float2bfloat16(rem);
        hs[i] = (uint32_t)__bfloat16_as_ushort(hb);
        ms[i] = (uint32_t)__bfloat16_as_ushort(mb);
    }
    uh = make_uint2(hs[0] | (hs[1] << 16), hs[2] | (hs[3] << 16));
    um = make_uint2(ms[0] | (ms[1] << 16), ms[2] | (ms[3] << 16));
}

// ---------------------------------------------------------------------------
// K1: histogram (4 edges/thread, atomic-latency-bound) + h pre-split riding
// in its latency shadow (grid-stride over 400k 8-float tasks). Resets g_total.
// ---------------------------------------------------------------------------
__global__ void hist_kernel(const int* __restrict__ dst,
                            const float* __restrict__ h) {
    int t = blockIdx.x * blockDim.x + threadIdx.x;
    if (t == 0) g_total = 0;
    if (t < N_EDGES / 4) {
        int4 d4 = reinterpret_cast<const int4*>(dst)[t];
        atomicAdd(&g_count[d4.x], 1);
        atomicAdd(&g_count[d4.y], 1);
        atomicAdd(&g_count[d4.z], 1);
        atomicAdd(&g_count[d4.w], 1);
    }
    // h -> bf16 hi/mid split (independent of the atomics above)
    const float4* __restrict__ h4 = reinterpret_cast<const float4*>(h);
    int nthreads = HIST_BLOCKS * 256;
    for (int task = t; task < N_NODES * D / 8; task += nthreads) {
        float v[8];
        float4 v0 = h4[task * 2];
        float4 v1 = h4[task * 2 + 1];
        v[0]=v0.x; v[1]=v0.y; v[2]=v0.z; v[3]=v0.w;
        v[4]=v1.x; v[5]=v1.y; v[6]=v1.z; v[7]=v1.w;
        uint4 uh, um; split8(v, uh, um);
        g_hh[task] = uh;
        g_hm[task] = um;
    }
}

// ---------------------------------------------------------------------------
// K2: reserve CSR slices (block scan + atomic base claim)
// ---------------------------------------------------------------------------
__global__ __launch_bounds__(SCAN_BLK) void reserve_kernel() {
    __shared__ int sh[SCAN_BLK];
    __shared__ int base_sh;
    int t = threadIdx.x;
    int i = blockIdx.x * SCAN_BLK + t;
    int c = (i < N_NODES) ? g_count[i] : 0;
    sh[t] = c;
    __syncthreads();
    for (int d = 1; d < SCAN_BLK; d <<= 1) {
        int v = (t >= d) ? sh[t - d] : 0;
        __syncthreads();
        sh[t] += v;
        __syncthreads();
    }
    if (t == SCAN_BLK - 1) base_sh = atomicAdd(&g_total, sh[t]);
    __syncthreads();
    if (i < N_NODES) {
        int v = base_sh + sh[t] - c;
        g_start[i]  = v;
        g_cursor[i] = v;
    }
}

// ---------------------------------------------------------------------------
// K3: position scatter (4 edges/thread)
// ---------------------------------------------------------------------------
__global__ void pos_kernel(const int* __restrict__ src,
                           const int* __restrict__ dst,
                           const float* __restrict__ w) {
    int t = blockIdx.x * blockDim.x + threadIdx.x;
    if (t >= N_EDGES / 4) return;
    int4   s4 = reinterpret_cast<const int4*>(src)[t];
    int4   d4 = reinterpret_cast<const int4*>(dst)[t];
    float4 w4 = reinterpret_cast<const float4*>(w)[t];
    int p0 = atomicAdd(&g_cursor[d4.x], 1);
    int p1 = atomicAdd(&g_cursor[d4.y], 1);
    int p2 = atomicAdd(&g_cursor[d4.z], 1);
    int p3 = atomicAdd(&g_cursor[d4.w], 1);
    EdgeRec r;
    r.s = s4.x; r.w = w4.x; g_edge[p0] = r;
    r.s = s4.y; r.w = w4.y; g_edge[p1] = r;
    r.s = s4.z; r.w = w4.z; g_edge[p2] = r;
    r.s = s4.w; r.w = w4.w; g_edge[p3] = r;
}

// ---------------------------------------------------------------------------
// K4: gather -> h_N written directly as bf16 hi/mid. Two nodes per warp
// (half-warp per node, lane owns a float4). Grid-stride at full residency.
// Zeroes g_count (invariant).
// ---------------------------------------------------------------------------
__global__ __launch_bounds__(256) void gather_kernel(const float* __restrict__ h) {
    int warp = threadIdx.x >> 5;
    int lane = threadIdx.x & 31;
    int hl   = lane & 15;            // lane within half-warp
    int hsel = lane & 16;            // 0 for node 2p, 16 for node 2p+1
    const float4* __restrict__ h4 = reinterpret_cast<const float4*>(h);

    int gw = blockIdx.x * 8 + warp;
    int nwarps = gridDim.x * 8;
    const int npairs = N_NODES / 2;  // 25000

    for (int p = gw; p < npairs; p += nwarps) {
        int n = p * 2 + (hsel >> 4);
        int beg = g_start[n];
        int cnt = g_count[n];
        int cntmax = max(cnt, __shfl_xor_sync(0xffffffffu, cnt, 16));

        float4 acc = make_float4(0.f, 0.f, 0.f, 0.f);

        for (int base = 0; base < cntmax; base += 16) {
            int   rs = 0;
            float rw = 0.f;
            if (base + hl < cnt) {
                EdgeRec r = g_edge[beg + base + hl];
                rs = r.s;
                rw = r.w;
            }
            int mm = cntmax - base;
            if (mm > 16) mm = 16;
            int j = 0;
            for (; j + 3 < mm; j += 4) {
                int   s0 = __shfl_sync(0xffffffffu, rs, j     + hsel);
                int   s1 = __shfl_sync(0xffffffffu, rs, j + 1 + hsel);
                int   s2 = __shfl_sync(0xffffffffu, rs, j + 2 + hsel);
                int   s3 = __shfl_sync(0xffffffffu, rs, j + 3 + hsel);
                float w0 = __shfl_sync(0xffffffffu, rw, j     + hsel);
                float w1 = __shfl_sync(0xffffffffu, rw, j + 1 + hsel);
                float w2 = __shfl_sync(0xffffffffu, rw, j + 2 + hsel);
                float w3 = __shfl_sync(0xffffffffu, rw, j + 3 + hsel);
                float4 a0 = h4[(size_t)s0 * 16 + hl];
                float4 a1 = h4[(size_t)s1 * 16 + hl];
                float4 a2 = h4[(size_t)s2 * 16 + hl];
                float4 a3 = h4[(size_t)s3 * 16 + hl];
                acc.x += a0.x * w0 + a1.x * w1 + a2.x * w2 + a3.x * w3;
                acc.y += a0.y * w0 + a1.y * w1 + a2.y * w2 + a3.y * w3;
                acc.z += a0.z * w0 + a1.z * w1 + a2.z * w2 + a3.z * w3;
                acc.w += a0.w * w0 + a1.w * w1 + a2.w * w2 + a3.w * w3;
            }
            for (; j < mm; j++) {
                int   s0 = __shfl_sync(0xffffffffu, rs, j + hsel);
                float w0 = __shfl_sync(0xffffffffu, rw, j + hsel);
                float4 a0 = h4[(size_t)s0 * 16 + hl];
                acc.x += a0.x * w0;
                acc.y += a0.y * w0;
                acc.z += a0.z * w0;
                acc.w += a0.w * w0;
            }
        }

        float inv = 1.0f / fmaxf((float)cnt, 1.0f);
        float4 r = make_float4(acc.x * inv, acc.y * inv, acc.z * inv, acc.w * inv);
        uint2 uh, um; split4(r, uh, um);
        reinterpret_cast<uint2*>(g_hnh)[(size_t)n * 16 + hl] = uh;
        reinterpret_cast<uint2*>(g_hnm)[(size_t)n * 16 + hl] = um;
        if (hl == 0) g_count[n] = 0;
    }
}

// ---------------------------------------------------------------------------
// K5: HMMA GEMM: out[tile 128, 64] = [h|h_N] @ W^T + b, bf16 3-split.
// A staging is now a PURE COPY from pre-split bf16 arrays (no split8).
// ---------------------------------------------------------------------------
__global__ __launch_bounds__(256)
void gemm_kernel(const float* __restrict__ W,
                 const float* __restrict__ b,
                 float* __restrict__ out) {
    extern __shared__ char smem[];
    uint32_t sb = s2u(smem);
    int tid = threadIdx.x;
    int wid = tid >> 5;
    int lane = tid & 31;
    int n0 = blockIdx.x * TILE_M;

    // ---- stage B (W -> Bh/Bm): split8 kept, only 4 tasks/thread ----
    #pragma unroll
    for (int it = 0; it < 4; it++) {
        int task = tid + 256 * it;
        int r = task >> 4;
        int c = task & 15;
        float v[8];
        const float4* p = reinterpret_cast<const float4*>(W + (size_t)r * D2 + c * 8);
        float4 v0 = p[0], v1 = p[1];
        v[0]=v0.x; v[1]=v0.y; v[2]=v0.z; v[3]=v0.w;
        v[4]=v1.x; v[5]=v1.y; v[6]=v1.z; v[7]=v1.w;
        uint4 uh, um; split8(v, uh, um);
        uint32_t off = (uint32_t)r * ASTRIDE + c * 16;
        *reinterpret_cast<uint4*>(smem + SM_BH + off) = uh;
        *reinterpret_cast<uint4*>(smem + SM_BM + off) = um;
    }

    // ---- stage A: pure copy from g_hh/g_hm (c<8) and g_hnh/g_hnm ----
    #pragma unroll
    for (int it = 0; it < 8; it++) {
        int task = tid + 256 * it;
        int r = task >> 4;
        int c = task & 15;
        int n = n0 + r;
        uint4 uh = make_uint4(0, 0, 0, 0);
        uint4 um = make_uint4(0, 0, 0, 0);
        if (n < N_NODES) {
            if (c < 8) {
                uh = g_hh[(size_t)n * 8 + c];
                um = g_hm[(size_t)n * 8 + c];
            } else {
                uh = g_hnh[(size_t)n * 8 + (c - 8)];
                um = g_hnm[(size_t)n * 8 + (c - 8)];
            }
        }
        uint32_t off = (uint32_t)r * ASTRIDE + c * 16;
        *reinterpret_cast<uint4*>(smem + SM_AH + off) = uh;
        *reinterpret_cast<uint4*>(smem + SM_AM + off) = um;
    }
    __syncthreads();

    // ---- compute ----
    float c[8][4];
    #pragma unroll
    for (int nc = 0; nc < 8; nc++)
        #pragma unroll
        for (int i = 0; i < 4; i++) c[nc][i] = 0.f;

    uint32_t arow = (lane & 7) + ((lane >> 3) & 1) * 8;
    uint32_t asel = (lane >> 4) * 16;
    uint32_t brow = lane & 7;
    uint32_t bsel = ((lane >> 3) & 1) * 16;

    #pragma unroll
    for (int ks = 0; ks < 8; ks++) {
        uint32_t acol = ks * 32 + asel;
        uint32_t aaddr = sb + SM_AH + (wid * 16 + arow) * ASTRIDE + acol;
        uint32_t ah[4], am[4];
        ldm_x4(ah[0], ah[1], ah[2], ah[3], aaddr);
        ldm_x4(am[0], am[1], am[2], am[3], aaddr + (SM_AM - SM_AH));

        uint32_t bcol = ks * 32 + bsel;
        #pragma unroll
        for (int nc = 0; nc < 8; nc++) {
            uint32_t baddr = sb + SM_BH + (nc * 8 + brow) * ASTRIDE + bcol;
            uint32_t bh0, bh1, bm0, bm1;
            ldm_x2(bh0, bh1, baddr);
            ldm_x2(bm0, bm1, baddr + (SM_BM - SM_BH));
            mma16816(c[nc], ah, bh0, bh1);   // hh
            mma16816(c[nc], ah, bm0, bm1);   // hm
            mma16816(c[nc], am, bh0, bh1);   // mh
        }
    }

    // ---- epilogue: bias + store ----
    int r0 = n0 + wid * 16 + (lane >> 2);
    int r1 = r0 + 8;
    int cb = (lane & 3) * 2;
    #pragma unroll
    for (int nc = 0; nc < 8; nc++) {
        int col = nc * 8 + cb;
        float2 bv = *reinterpret_cast<const float2*>(b + col);
        if (r0 < N_NODES)
            *reinterpret_cast<float2*>(out + (size_t)r0 * D + col) =
                make_float2(c[nc][0] + bv.x, c[nc][1] + bv.y);
        if (r1 < N_NODES)
            *reinterpret_cast<float2*>(out + (size_t)r1 * D + col) =
                make_float2(c[nc][2] + bv.x, c[nc][3] + bv.y);
    }
}

// ---------------------------------------------------------------------------
// Launch — 5 kernels
// ---------------------------------------------------------------------------
extern "C" void kernel_launch(void* const* d_in, const int* in_sizes, int n_in,
                              void* d_out, int out_size) {
    const float* h   = (const float*)d_in[0];
    const float* w   = (const float*)d_in[1];
    const int*   src = (const int*)  d_in[2];
    const int*   dst = (const int*)  d_in[3];
    const float* W   = (const float*)d_in[4];
    const float* b   = (const float*)d_in[5];
    float* out = (float*)d_out;

    (void)in_sizes; (void)n_in; (void)out_size;

    static bool attr_set = false;
    if (!attr_set) {
        cudaFuncSetAttribute(gemm_kernel,
                             cudaFuncAttributeMaxDynamicSharedMemorySize, SM_TOTAL);
        attr_set = true;
    }

    hist_kernel<<<HIST_BLOCKS, 256>>>(dst, h);
    reserve_kernel<<<NBLK_SCAN, SCAN_BLK>>>();
    pos_kernel<<<(N_EDGES / 4 + 255) / 256, 256>>>(src, dst, w);
    gather_kernel<<<GATHER_BLOCKS, 256>>>(h);
    gemm_kernel<<<N_TILES, 256, SM_TOTAL>>>(W, b, out);
}

// round 17
// speedup vs baseline: 1.0039x; 1.0039x over previous
#include <cuda_runtime.h>
#include <cuda_bf16.h>
#include <cstdint>

#define N_NODES 50000
#define N_EDGES 800000
#define D 64
#define D2 128

#define SCAN_BLK 1024
#define NBLK_SCAN 49

#define TILE_M 128
#define N_TILES ((N_NODES + TILE_M - 1) / TILE_M)   // 391

// gemm_hy smem: A = h tile (K=64), B = [W1|W2] (128 out-rows, K=64), bf16
// hi/mid. Row stride 144B (36 words -> 4-bank shift/row, conflict-free
// ldmatrix/STS). Total 72KB -> 3 CTAs/SM (single wave for 391 tiles).
#define A2STRIDE 144
#define SM2_AH 0
#define SM2_AM (SM2_AH + TILE_M * A2STRIDE)   // 18432
#define SM2_BH (SM2_AM + TILE_M * A2STRIDE)   // 36864
#define SM2_BM (SM2_BH + 128 * A2STRIDE)      // 55296
#define SM2_TOTAL (SM2_BM + 128 * A2STRIDE)   // 73728

#define GATHER_BLOCKS 888    // 6 CTAs/SM x 148

// ---------------------------------------------------------------------------
// Scratch
// ---------------------------------------------------------------------------
struct __align__(8) EdgeRec { int s; float w; };

__device__ int     g_count[N_NODES];
__device__ int     g_start[N_NODES];
__device__ int     g_cursor[N_NODES];
__device__ int     g_total;
__device__ EdgeRec g_edge[N_EDGES];
__device__ float   g_z[N_NODES * D];   // h @ W1^T + b
__device__ float   g_y[N_NODES * D];   // h @ W2^T

// ---------------------------------------------------------------------------
// helpers
// ---------------------------------------------------------------------------
__device__ __forceinline__ uint32_t s2u(const void* p) {
    uint32_t a;
    asm("{ .reg .u64 t; cvta.to.shared.u64 t, %1; cvt.u32.u64 %0, t; }" : "=r"(a) : "l"(p));
    return a;
}

__device__ __forceinline__ void ldm_x4(uint32_t& r0, uint32_t& r1,
                                       uint32_t& r2, uint32_t& r3, uint32_t a) {
    asm volatile("ldmatrix.sync.aligned.m8n8.x4.shared.b16 {%0,%1,%2,%3}, [%4];"
                 : "=r"(r0), "=r"(r1), "=r"(r2), "=r"(r3) : "r"(a));
}
__device__ __forceinline__ void ldm_x2(uint32_t& r0, uint32_t& r1, uint32_t a) {
    asm volatile("ldmatrix.sync.aligned.m8n8.x2.shared.b16 {%0,%1}, [%2];"
                 : "=r"(r0), "=r"(r1) : "r"(a));
}
__device__ __forceinline__ void mma16816(float* c, const uint32_t* a,
                                         uint32_t b0, uint32_t b1) {
    asm volatile("mma.sync.aligned.m16n8k16.row.col.f32.bf16.bf16.f32 "
                 "{%0,%1,%2,%3}, {%4,%5,%6,%7}, {%8,%9}, {%0,%1,%2,%3};"
                 : "+f"(c[0]), "+f"(c[1]), "+f"(c[2]), "+f"(c[3])
                 : "r"(a[0]), "r"(a[1]), "r"(a[2]), "r"(a[3]), "r"(b0), "r"(b1));
}

__device__ __forceinline__ void split8(const float* v, uint4& uh, uint4& um) {
    uint32_t hs[8], ms[8];
    #pragma unroll
    for (int i = 0; i < 8; i++) {
        __nv_bfloat16 hb = __float2bfloat16(v[i]);
        float rem = v[i] - __bfloat162float(hb);
        __nv_bfloat16 mb = __float2bfloat16(rem);
        hs[i] = (uint32_t)__bfloat16_as_ushort(hb);
        ms[i] = (uint32_t)__bfloat16_as_ushort(mb);
    }
    uh = make_uint4(hs[0] | (hs[1] << 16), hs[2] | (hs[3] << 16),
                    hs[4] | (hs[5] << 16), hs[6] | (hs[7] << 16));
    um = make_uint4(ms[0] | (ms[1] << 16), ms[2] | (ms[3] << 16),
                    ms[4] | (ms[5] << 16), ms[6] | (ms[7] << 16));
}

// ---------------------------------------------------------------------------
// K1: histogram (4 edges/thread); resets g_total
// ---------------------------------------------------------------------------
__global__ void hist_kernel(const int* __restrict__ dst) {
    int t = blockIdx.x * blockDim.x + threadIdx.x;
    if (t == 0) g_total = 0;
    if (t >= N_EDGES / 4) return;
    int4 d4 = reinterpret_cast<const int4*>(dst)[t];
    atomicAdd(&g_count[d4.x], 1);
    atomicAdd(&g_count[d4.y], 1);
    atomicAdd(&g_count[d4.z], 1);
    atomicAdd(&g_count[d4.w], 1);
}

// ---------------------------------------------------------------------------
// K2: reserve CSR slices (block scan + atomic base claim)
// ---------------------------------------------------------------------------
__global__ __launch_bounds__(SCAN_BLK) void reserve_kernel() {
    __shared__ int sh[SCAN_BLK];
    __shared__ int base_sh;
    int t = threadIdx.x;
    int i = blockIdx.x * SCAN_BLK + t;
    int c = (i < N_NODES) ? g_count[i] : 0;
    sh[t] = c;
    __syncthreads();
    for (int d = 1; d < SCAN_BLK; d <<= 1) {
        int v = (t >= d) ? sh[t - d] : 0;
        __syncthreads();
        sh[t] += v;
        __syncthreads();
    }
    if (t == SCAN_BLK - 1) base_sh = atomicAdd(&g_total, sh[t]);
    __syncthreads();
    if (i < N_NODES) {
        int v = base_sh + sh[t] - c;
        g_start[i]  = v;
        g_cursor[i] = v;
    }
}

// ---------------------------------------------------------------------------
// K3: position scatter (4 edges/thread)
// ---------------------------------------------------------------------------
__global__ void pos_kernel(const int* __restrict__ src,
                           const int* __restrict__ dst,
                           const float* __restrict__ w) {
    int t = blockIdx.x * blockDim.x + threadIdx.x;
    if (t >= N_EDGES / 4) return;
    int4   s4 = reinterpret_cast<const int4*>(src)[t];
    int4   d4 = reinterpret_cast<const int4*>(dst)[t];
    float4 w4 = reinterpret_cast<const float4*>(w)[t];
    int p0 = atomicAdd(&g_cursor[d4.x], 1);
    int p1 = atomicAdd(&g_cursor[d4.y], 1);
    int p2 = atomicAdd(&g_cursor[d4.z], 1);
    int p3 = atomicAdd(&g_cursor[d4.w], 1);
    EdgeRec r;
    r.s = s4.x; r.w = w4.x; g_edge[p0] = r;
    r.s = s4.y; r.w = w4.y; g_edge[p1] = r;
    r.s = s4.z; r.w = w4.z; g_edge[p2] = r;
    r.s = s4.w; r.w = w4.w; g_edge[p3] = r;
}

// ---------------------------------------------------------------------------
// K4: gemm_hy — [z | y] = h @ [W1 | W2]^T (+b on z), bf16 3-split HMMA.
// A = h tile (128 x K=64). B = 128 output rows: o<64 -> W[o][0:64] (z),
// o>=64 -> W[o-64][64:128] (y). Two n-pass halves to cap registers.
// Runs on LINEARITY: out = z + gather(w*y)/deg, so no gather dependency.
// ---------------------------------------------------------------------------
__global__ __launch_bounds__(256)
void gemm_hy_kernel(const float* __restrict__ h,
                    const float* __restrict__ W,
                    const float* __restrict__ b) {
    extern __shared__ char smem[];
    uint32_t sb = s2u(smem);
    int tid = threadIdx.x;
    int wid = tid >> 5;
    int lane = tid & 31;
    int n0 = blockIdx.x * TILE_M;

    // ---- stage A (h -> Ah/Am): 1024 tasks of 8 floats ----
    #pragma unroll
    for (int it = 0; it < 4; it++) {
        int task = tid + 256 * it;
        int r = task >> 3;            // node row 0..127
        int c = task & 7;             // 8-float chunk of K=64
        int n = n0 + r;
        float v[8];
        if (n < N_NODES) {
            const float4* p = reinterpret_cast<const float4*>(h + (size_t)n * D + c * 8);
            float4 v0 = p[0], v1 = p[1];
            v[0]=v0.x; v[1]=v0.y; v[2]=v0.z; v[3]=v0.w;
            v[4]=v1.x; v[5]=v1.y; v[6]=v1.z; v[7]=v1.w;
        } else {
            #pragma unroll
            for (int i = 0; i < 8; i++) v[i] = 0.f;
        }
        uint4 uh, um; split8(v, uh, um);
        uint32_t off = (uint32_t)r * A2STRIDE + c * 16;
        *reinterpret_cast<uint4*>(smem + SM2_AH + off) = uh;
        *reinterpret_cast<uint4*>(smem + SM2_AM + off) = um;
    }

    // ---- stage B ([W1|W2] -> Bh/Bm): 1024 tasks ----
    #pragma unroll
    for (int it = 0; it < 4; it++) {
        int task = tid + 256 * it;
        int r = task >> 3;            // output row o 0..127
        int c = task & 7;             // chunk of K=64
        const float* wp = W + (size_t)(r & 63) * D2 + ((r >> 6) << 6) + c * 8;
        const float4* p = reinterpret_cast<const float4*>(wp);
        float v[8];
        float4 v0 = p[0], v1 = p[1];
        v[0]=v0.x; v[1]=v0.y; v[2]=v0.z; v[3]=v0.w;
        v[4]=v1.x; v[5]=v1.y; v[6]=v1.z; v[7]=v1.w;
        uint4 uh, um; split8(v, uh, um);
        uint32_t off = (uint32_t)r * A2STRIDE + c * 16;
        *reinterpret_cast<uint4*>(smem + SM2_BH + off) = uh;
        *reinterpret_cast<uint4*>(smem + SM2_BM + off) = um;
    }
    __syncthreads();

    uint32_t arow = (lane & 7) + ((lane >> 3) & 1) * 8;
    uint32_t asel = (lane >> 4) * 16;
    uint32_t brow = lane & 7;
    uint32_t bsel = ((lane >> 3) & 1) * 16;

    int r0 = n0 + wid * 16 + (lane >> 2);
    int r1 = r0 + 8;
    int cb = (lane & 3) * 2;

    #pragma unroll
    for (int pass = 0; pass < 2; pass++) {
        float c[8][4];
        #pragma unroll
        for (int nc = 0; nc < 8; nc++)
            #pragma unroll
            for (int i = 0; i < 4; i++) c[nc][i] = 0.f;

        #pragma unroll
        for (int ks = 0; ks < 4; ks++) {
            uint32_t acol = ks * 32 + asel;
            uint32_t aaddr = sb + SM2_AH + (wid * 16 + arow) * A2STRIDE + acol;
            uint32_t ah[4], am[4];
            ldm_x4(ah[0], ah[1], ah[2], ah[3], aaddr);
            ldm_x4(am[0], am[1], am[2], am[3], aaddr + (SM2_AM - SM2_AH));

            uint32_t bcol = ks * 32 + bsel;
            #pragma unroll
            for (int nc = 0; nc < 8; nc++) {
                int ncg = pass * 8 + nc;
                uint32_t baddr = sb + SM2_BH + (ncg * 8 + brow) * A2STRIDE + bcol;
                uint32_t bh0, bh1, bm0, bm1;
                ldm_x2(bh0, bh1, baddr);
                ldm_x2(bm0, bm1, baddr + (SM2_BM - SM2_BH));
                mma16816(c[nc], ah, bh0, bh1);   // hh
                mma16816(c[nc], ah, bm0, bm1);   // hm
                mma16816(c[nc], am, bh0, bh1);   // mh
            }
        }

        // epilogue: pass 0 -> z (+bias), pass 1 -> y
        float* dstp = (pass == 0) ? g_z : g_y;
        #pragma unroll
        for (int nc = 0; nc < 8; nc++) {
            int col = nc * 8 + cb;
            float bx = 0.f, by = 0.f;
            if (pass == 0) {
                float2 bv = *reinterpret_cast<const float2*>(b + col);
                bx = bv.x; by = bv.y;
            }
            if (r0 < N_NODES)
                *reinterpret_cast<float2*>(dstp + (size_t)r0 * D + col) =
                    make_float2(c[nc][0] + bx, c[nc][1] + by);
            if (r1 < N_NODES)
                *reinterpret_cast<float2*>(dstp + (size_t)r1 * D + col) =
                    make_float2(c[nc][2] + bx, c[nc][3] + by);
        }
    }
}

// ---------------------------------------------------------------------------
// K5: gather_final — out[n] = z[n] + (sum_e w_e * y[src_e]) / max(deg,1).
// Two nodes per warp (half-warp per node, lane owns float4), grid-stride,
// __launch_bounds__(256,6) caps regs at 42 -> 75% occ. Zeroes g_count.
// ---------------------------------------------------------------------------
__global__ __launch_bounds__(256, 6)
void gather_final_kernel(float* __restrict__ out) {
    int warp = threadIdx.x >> 5;
    int lane = threadIdx.x & 31;
    int hl   = lane & 15;
    int hsel = lane & 16;
    const float4* __restrict__ y4 = reinterpret_cast<const float4*>(g_y);
    const float4* __restrict__ z4 = reinterpret_cast<const float4*>(g_z);

    int gw = blockIdx.x * 8 + warp;
    int nwarps = gridDim.x * 8;
    const int npairs = N_NODES / 2;

    for (int p = gw; p < npairs; p += nwarps) {
        int n = p * 2 + (hsel >> 4);
        int beg = g_start[n];
        int cnt = g_count[n];
        int cntmax = max(cnt, __shfl_xor_sync(0xffffffffu, cnt, 16));

        float4 acc = make_float4(0.f, 0.f, 0.f, 0.f);

        for (int base = 0; base < cntmax; base += 16) {
            int   rs = 0;
            float rw = 0.f;
            if (base + hl < cnt) {
                EdgeRec r = g_edge[beg + base + hl];
                rs = r.s;
                rw = r.w;
            }
            int mm = cntmax - base;
            if (mm > 16) mm = 16;
            int j = 0;
            for (; j + 3 < mm; j += 4) {
                int   s0 = __shfl_sync(0xffffffffu, rs, j     + hsel);
                int   s1 = __shfl_sync(0xffffffffu, rs, j + 1 + hsel);
                int   s2 = __shfl_sync(0xffffffffu, rs, j + 2 + hsel);
                int   s3 = __shfl_sync(0xffffffffu, rs, j + 3 + hsel);
                float w0 = __shfl_sync(0xffffffffu, rw, j     + hsel);
                float w1 = __shfl_sync(0xffffffffu, rw, j + 1 + hsel);
                float w2 = __shfl_sync(0xffffffffu, rw, j + 2 + hsel);
                float w3 = __shfl_sync(0xffffffffu, rw, j + 3 + hsel);
                float4 a0 = y4[(size_t)s0 * 16 + hl];
                float4 a1 = y4[(size_t)s1 * 16 + hl];
                float4 a2 = y4[(size_t)s2 * 16 + hl];
                float4 a3 = y4[(size_t)s3 * 16 + hl];
                acc.x += a0.x * w0 + a1.x * w1 + a2.x * w2 + a3.x * w3;
                acc.y += a0.y * w0 + a1.y * w1 + a2.y * w2 + a3.y * w3;
                acc.z += a0.z * w0 + a1.z * w1 + a2.z * w2 + a3.z * w3;
                acc.w += a0.w * w0 + a1.w * w1 + a2.w * w2 + a3.w * w3;
            }
            for (; j < mm; j++) {
                int   s0 = __shfl_sync(0xffffffffu, rs, j + hsel);
                float w0 = __shfl_sync(0xffffffffu, rw, j + hsel);
                float4 a0 = y4[(size_t)s0 * 16 + hl];
                acc.x += a0.x * w0;
                acc.y += a0.y * w0;
                acc.z += a0.z * w0;
                acc.w += a0.w * w0;
            }
        }

        float inv = 1.0f / fmaxf((float)cnt, 1.0f);
        float4 zv = z4[(size_t)n * 16 + hl];
        reinterpret_cast<float4*>(out)[(size_t)n * 16 + hl] =
            make_float4(acc.x * inv + zv.x, acc.y * inv + zv.y,
                        acc.z * inv + zv.z, acc.w * inv + zv.w);
        if (hl == 0) g_count[n] = 0;
    }
}

// ---------------------------------------------------------------------------
// Launch — 5 kernels
// ---------------------------------------------------------------------------
extern "C" void kernel_launch(void* const* d_in, const int* in_sizes, int n_in,
                              void* d_out, int out_size) {
    const float* h   = (const float*)d_in[0];
    const float* w   = (const float*)d_in[1];
    const int*   src = (const int*)  d_in[2];
    const int*   dst = (const int*)  d_in[3];
    const float* W   = (const float*)d_in[4];
    const float* b   = (const float*)d_in[5];
    float* out = (float*)d_out;

    (void)in_sizes; (void)n_in; (void)out_size;

    static bool attr_set = false;
    if (!attr_set) {
        cudaFuncSetAttribute(gemm_hy_kernel,
                             cudaFuncAttributeMaxDynamicSharedMemorySize, SM2_TOTAL);
        attr_set = true;
    }

    hist_kernel<<<(N_EDGES / 4 + 255) / 256, 256>>>(dst);
    reserve_kernel<<<NBLK_SCAN, SCAN_BLK>>>();
    pos_kernel<<<(N_EDGES / 4 + 255) / 256, 256>>>(src, dst, w);
    gemm_hy_kernel<<<N_TILES, 256, SM2_TOTAL>>>(h, W, b);
    gather_final_kernel<<<GATHER_BLOCKS, 256>>>(out);
}